// round 1
// baseline (speedup 1.0000x reference)
#include <cuda_runtime.h>

// ESN: h_t = tanh(x_t @ W_in^T + h_{t-1} @ W_res^T), output h_{T-1} as [B,H] fp32.
// B=64, T=512, I=128, H=2048.
//
// Design (round 1, fp32 SIMT):
//  - One kernel per timestep (512 graph nodes) -> no grid-barrier hazards.
//  - K dimension = I + H = 2176, split 8 ways (KC=272); N split 16 ways (BN=128).
//    grid = 128 CTAs = one wave on GB300.
//  - Each CTA stages its W tile [128 x 272] (k-major, padded) and the activation
//    slice v[272 x 64] (h stored TRANSPOSED [k][b]) into 213 KB smem, then runs a
//    packed-fp32 (fma.rn.f32x2) register-tiled GEMM: 8 b x 4 j per thread.
//  - Partial sums go to a global scratch; the 8th CTA per column-group (atomic
//    ticket) reduces, applies tanhf, writes ping-ponged h^T, and on the last
//    step also writes d_out in [b][j] layout.

#define BB   64
#define TT   512
#define II   128
#define HH   2048
#define KTOT (II + HH)        // 2176
#define NSPL 8
#define KC   (KTOT / NSPL)    // 272
#define NJG  16
#define BN   (HH / NJG)       // 128
#define WPAD 132              // row stride (floats) for k-major W tile in smem
#define NTHR 256

#define SMEM_BYTES ((KC * WPAD + KC * BB) * 4)   // 143616 + 69632 = 213248 B

__device__ float    g_h[2][HH * BB];                 // ping-pong h, TRANSPOSED: [j][b]
__device__ float    g_part[NSPL * NJG * BN * BB];    // split-K partials
__device__ unsigned g_ticket[NJG];

typedef unsigned long long u64;

__device__ __forceinline__ u64 pack2(float lo, float hi) {
    u64 r;
    asm("mov.b64 %0, {%1, %2};" : "=l"(r) : "f"(lo), "f"(hi));
    return r;
}
__device__ __forceinline__ void fma2(u64 &acc, u64 a, u64 b) {
    asm("fma.rn.f32x2 %0, %1, %2, %0;" : "+l"(acc) : "l"(a), "l"(b));
}

__global__ void esn_init() {
    int i = blockIdx.x * blockDim.x + threadIdx.x;
    int n = gridDim.x * blockDim.x;
    for (int o = i; o < HH * BB; o += n) g_h[0][o] = 0.0f;
    if (i < NJG) g_ticket[i] = 0u;
}

__global__ __launch_bounds__(NTHR, 1) void esn_step(
    const float* __restrict__ x,     // [B, T, I]
    const float* __restrict__ Win,   // [H, I]
    const float* __restrict__ Wres,  // [H, H]
    float* __restrict__ out,         // [B, H]
    int t)
{
    extern __shared__ float smem[];
    float* sW = smem;                 // [KC][WPAD]  k-major
    float* sV = smem + KC * WPAD;     // [KC][BB]

    const int tid   = threadIdx.x;
    const int jg    = blockIdx.x >> 3;   // 0..15  (column group)
    const int ks    = blockIdx.x & 7;    // 0..7   (K split)
    const int kbase = ks * KC;

    const float* __restrict__ hprev = g_h[t & 1];
    float* __restrict__       hnext = g_h[(t + 1) & 1];

    // ---- stage W tile (coalesced global reads along k) ----
    for (int idx = tid; idx < BN * KC; idx += NTHR) {
        int j  = idx / KC;
        int k  = idx - j * KC;
        int kg = kbase + k;
        int jgl = jg * BN + j;
        float w = (kg < II) ? Win[jgl * II + kg] : Wres[jgl * HH + (kg - II)];
        sW[k * WPAD + j] = w;
    }
    // ---- stage activation slice: x part (strided) or h^T part (contiguous) ----
    for (int idx = tid; idx < KC * BB; idx += NTHR) {
        int k  = idx >> 6;
        int b  = idx & 63;
        int kg = kbase + k;
        float v = (kg < II) ? x[(b * TT + t) * II + kg]
                            : hprev[(kg - II) * BB + b];
        sV[idx] = v;
    }
    __syncthreads();

    // ---- register-tiled GEMM: thread = (bq, jq); 8 b (4 pairs) x 4 j ----
    const int jq = tid & 31;    // j0 = jq*4
    const int bq = tid >> 5;    // b0 = bq*8

    u64 acc[4][4];
#pragma unroll
    for (int p = 0; p < 4; p++)
#pragma unroll
        for (int jj = 0; jj < 4; jj++) acc[p][jj] = 0ull;

    const u64*    pV = (const u64*)sV + bq * 4;  // row = 32 u64
    const float4* pW = (const float4*)sW;        // row = 33 float4

#pragma unroll 4
    for (int k = 0; k < KC; k++) {
        const u64* vr = pV + k * 32;
        u64 h0 = vr[0], h1 = vr[1], h2 = vr[2], h3 = vr[3];   // broadcast LDS
        float4 w4 = pW[k * 33 + jq];
        u64 w0 = pack2(w4.x, w4.x);
        u64 w1 = pack2(w4.y, w4.y);
        u64 w2 = pack2(w4.z, w4.z);
        u64 w3 = pack2(w4.w, w4.w);
        fma2(acc[0][0], h0, w0); fma2(acc[1][0], h1, w0);
        fma2(acc[2][0], h2, w0); fma2(acc[3][0], h3, w0);
        fma2(acc[0][1], h0, w1); fma2(acc[1][1], h1, w1);
        fma2(acc[2][1], h2, w1); fma2(acc[3][1], h3, w1);
        fma2(acc[0][2], h0, w2); fma2(acc[1][2], h1, w2);
        fma2(acc[2][2], h2, w2); fma2(acc[3][2], h3, w2);
        fma2(acc[0][3], h0, w3); fma2(acc[1][3], h1, w3);
        fma2(acc[2][3], h2, w3); fma2(acc[3][3], h3, w3);
    }

    // ---- write partials: layout o = j*64 + b (matches h^T), b-pairs as u64 ----
    float* P = g_part + (ks * NJG + jg) * (BN * BB);
#pragma unroll
    for (int jj = 0; jj < 4; jj++) {
        int j = jq * 4 + jj;
#pragma unroll
        for (int p = 0; p < 4; p++) {
            int b = bq * 8 + p * 2;
            *(u64*)&P[j * BB + b] = acc[p][jj];
        }
    }

    __threadfence();
    __syncthreads();
    __shared__ unsigned sLast;
    if (tid == 0) {
        unsigned old = atomicAdd(&g_ticket[jg], 1u);
        sLast = (old == NSPL - 1) ? 1u : 0u;
    }
    __syncthreads();

    if (sLast) {
        __threadfence();   // acquire side of fence/fence pattern
        const bool last_t = (t == TT - 1);
        const int  tile   = BN * BB;     // 8192
        for (int o4 = tid; o4 < tile / 4; o4 += NTHR) {
            float4 s = make_float4(0.f, 0.f, 0.f, 0.f);
#pragma unroll
            for (int kr = 0; kr < NSPL; kr++) {
                const float4 v = *(const float4*)(g_part + (kr * NJG + jg) * tile + o4 * 4);
                s.x += v.x; s.y += v.y; s.z += v.z; s.w += v.w;
            }
            s.x = tanhf(s.x); s.y = tanhf(s.y); s.z = tanhf(s.z); s.w = tanhf(s.w);
            *(float4*)&hnext[jg * tile + o4 * 4] = s;
            if (last_t) {
                int o = o4 * 4;
                int j = o >> 6;          // o = j*64 + b, b multiple of 4 here
                int b = o & 63;
                int jgl = jg * BN + j;
                out[(b + 0) * HH + jgl] = s.x;
                out[(b + 1) * HH + jgl] = s.y;
                out[(b + 2) * HH + jgl] = s.z;
                out[(b + 3) * HH + jgl] = s.w;
            }
        }
        if (tid == 0) g_ticket[jg] = 0u;   // visible to next launch via kernel boundary
    }
}

extern "C" void kernel_launch(void* const* d_in, const int* in_sizes, int n_in,
                              void* d_out, int out_size)
{
    const float* x    = (const float*)d_in[0];
    const float* Win  = (const float*)d_in[1];
    const float* Wres = (const float*)d_in[2];
    float* out = (float*)d_out;

    cudaFuncSetAttribute(esn_step, cudaFuncAttributeMaxDynamicSharedMemorySize, SMEM_BYTES);

    esn_init<<<128, 256>>>();
    for (int t = 0; t < TT; t++) {
        esn_step<<<NJG * NSPL, NTHR, SMEM_BYTES>>>(x, Win, Wres, out, t);
    }
}

// round 3
// speedup vs baseline: 2.8122x; 2.8122x over previous
#include <cuda_runtime.h>
#include <cuda_bf16.h>
#include <cstdint>

// ESN: h_t = tanh(x_t @ W_in^T + h_{t-1} @ W_res^T); out = h_{T-1} [B,H] fp32.
// B=64, T=512, I=128, H=2048.
//
// Round 3: warp-level mma.sync bf16 (baseline PTX — harness targets compute_103,
// so tcgen05/sm_103a-only instructions are unavailable). fp32 emulated as
// 3 bf16 MMAs: Wh*vh + Wh*vl + Wl*vh, fp32 register accumulators.
//
// Grid/step: 16 j-groups x 9 K-splits = 144 CTAs (one wave).
//   ks=0  : K=128 (x @ W_in^T),  ks=1..8 : K=256 each (h @ W_res^T).
// W pre-packed ONCE into exact m16n8k16 A-fragment layout in global: one
// coalesced LDG.128 per warp per k-chunk per term. v (h or x, bf16 hi/lo)
// staged per step into smem, natural [b][k] rows padded to 528 B so the
// B-fragment LDS.32 pattern is bank-conflict-free.
// Split-K partials -> atomic ticket -> 9-way reduce + tanhf -> resplit h.

#define BB   64
#define TT   512
#define II   128
#define HH   2048
#define KTOT (II + HH)
#define NJG  16
#define NKS  9
#define KC1  256
#define NTHR 256
#define SLOT 131072              // per (jg,ks): 2 terms x up to 64KB
#define VSTRIDE 528              // padded bytes per b-row in smem
#define VOFF  (BB * VSTRIDE)     // 33792: offset of lo tile
#define DYN_SMEM (2 * BB * VSTRIDE)   // 67584

// ---------------- device globals ----------------
__device__ __align__(16) unsigned char  g_wa[NJG * NKS * SLOT];   // ~18.9MB frag-packed W
__device__ __align__(16) __nv_bfloat16  g_xh[BB * TT * II];
__device__ __align__(16) __nv_bfloat16  g_xl[BB * TT * II];
__device__ __align__(16) __nv_bfloat16  g_hh[2][BB * HH];
__device__ __align__(16) __nv_bfloat16  g_hl[2][BB * HH];
__device__ float    g_part[NKS * NJG * 128 * BB];
__device__ unsigned g_ticket[NJG];

// ---------------- mma helper ----------------
__device__ __forceinline__ void mma_bf16(float* d, const uint32_t* a,
                                         uint32_t b0, uint32_t b1) {
    asm volatile(
        "mma.sync.aligned.m16n8k16.row.col.f32.bf16.bf16.f32 "
        "{%0,%1,%2,%3}, {%4,%5,%6,%7}, {%8,%9}, {%0,%1,%2,%3};"
        : "+f"(d[0]), "+f"(d[1]), "+f"(d[2]), "+f"(d[3])
        : "r"(a[0]), "r"(a[1]), "r"(a[2]), "r"(a[3]), "r"(b0), "r"(b1));
}

// ---------------- prep kernels ----------------
// Pack W (hi/lo bf16) into A-fragment layout:
//   frag uint4 at ((band*kch + kc)*32 + lane)*16; .x=a0 .y=a1 .z=a2 .w=a3
//   a0:(row g, k0,k0+1)  a1:(g+8, k0..)  a2:(g, k0+8..)  a3:(g+8, k0+8..)
//   g = lane>>2, k0 = (lane&3)*2  (k within 16-chunk)
__global__ void esn_prep_w(const float* __restrict__ Win, const float* __restrict__ Wres) {
    const int total = HH * KTOT;
    for (int idx = blockIdx.x * blockDim.x + threadIdx.x; idx < total;
         idx += gridDim.x * blockDim.x) {
        int j = idx / KTOT;
        int k = idx % KTOT;
        int jg = j >> 7, jl = j & 127;
        int ks, kl, kch;
        float w;
        if (k < II) { ks = 0; kl = k; kch = II >> 4; w = Win[j * II + k]; }
        else { int kk = k - II; ks = 1 + (kk >> 8); kl = kk & 255; kch = KC1 >> 4;
               w = Wres[j * HH + kk]; }
        __nv_bfloat16 hi = __float2bfloat16(w);
        float r = w - __bfloat162float(hi);
        __nv_bfloat16 lo = __float2bfloat16(r);

        int band = jl >> 4;
        int jr   = jl & 15;
        int kc   = kl >> 4;
        int kin  = kl & 15;
        int lane = ((jr & 7) << 2) | ((kin >> 1) & 3);
        int reg  = (jr >> 3) + ((kin >> 3) & 1) * 2;
        int half = kin & 1;
        unsigned off = (unsigned)(((band * kch + kc) * 32 + lane) * 16 + reg * 4 + half * 2);
        unsigned base = (unsigned)(jg * NKS + ks) * SLOT;
        unsigned tsz  = (unsigned)kch * 4096;   // bytes per term
        *(__nv_bfloat16*)(g_wa + base + off)       = hi;
        *(__nv_bfloat16*)(g_wa + base + tsz + off) = lo;
    }
}

__global__ void esn_prep_x(const float* __restrict__ x) {
    const int total = BB * TT * II;
    for (int idx = blockIdx.x * blockDim.x + threadIdx.x; idx < total;
         idx += gridDim.x * blockDim.x) {
        float v = x[idx];
        __nv_bfloat16 hi = __float2bfloat16(v);
        float r = v - __bfloat162float(hi);
        g_xh[idx] = hi;
        g_xl[idx] = __float2bfloat16(r);
    }
}

__global__ void esn_init() {
    int i = blockIdx.x * blockDim.x + threadIdx.x;
    int n = gridDim.x * blockDim.x;
    const __nv_bfloat16 z = __float2bfloat16(0.0f);
    for (int o = i; o < BB * HH; o += n) { g_hh[0][o] = z; g_hl[0][o] = z; }
    if (i < NJG) g_ticket[i] = 0u;
}

// ---------------- per-step kernel ----------------
__global__ __launch_bounds__(NTHR, 1) void esn_step(float* __restrict__ out, int t) {
    extern __shared__ __align__(16) unsigned char sm[];

    const int tid  = threadIdx.x;
    const int band = tid >> 5;         // warp id = j band (0..7)
    const int l    = tid & 31;
    const int jg   = blockIdx.x / NKS;
    const int ks   = blockIdx.x % NKS;
    const int KC   = ks ? KC1 : II;
    const int kch  = KC >> 4;

    // ---- stage v (hi/lo) into padded smem rows ----
    {
        const __nv_bfloat16* hsrc_h = g_hh[t & 1];
        const __nv_bfloat16* hsrc_l = g_hl[t & 1];
        const int cpb = KC >> 3;                 // 16B chunks per row
        const int chunks = BB * cpb;
        for (int i = tid; i < chunks; i += NTHR) {
            int b = i / cpb, c = i - b * cpb;
            const uint4 *s0, *s1;
            if (ks == 0) {
                int e = (b * TT + t) * II + c * 8;
                s0 = (const uint4*)(g_xh + e); s1 = (const uint4*)(g_xl + e);
            } else {
                int e = b * HH + (ks - 1) * KC1 + c * 8;
                s0 = (const uint4*)(hsrc_h + e); s1 = (const uint4*)(hsrc_l + e);
            }
            unsigned d = (unsigned)(b * VSTRIDE + c * 16);
            *(uint4*)(sm + d)        = *s0;
            *(uint4*)(sm + VOFF + d) = *s1;
        }
    }
    __syncthreads();

    // ---- register-tiled MMA: warp = 16j x 64b, 3 terms ----
    float acc[8][4];
#pragma unroll
    for (int nf = 0; nf < 8; nf++)
#pragma unroll
        for (int i = 0; i < 4; i++) acc[nf][i] = 0.0f;

    const unsigned slot = (unsigned)(jg * NKS + ks) * SLOT;
    const uint4* __restrict__ pAh = (const uint4*)(g_wa + slot) + (band * kch) * 32 + l;
    const uint4* __restrict__ pAl = pAh + (unsigned)kch * 256;   // + termsize/16

    // B lds base for this lane: row b = nf*8 + (l>>2), byte k = kc*32 + (l&3)*4
    const unsigned bbase = (unsigned)((l >> 2) * VSTRIDE + (l & 3) * 4);

    uint4 ah = *pAh, al = *pAl;
    for (int kc = 0; kc < kch; kc++) {
        uint4 ahn, aln;
        if (kc + 1 < kch) { ahn = pAh[(kc + 1) * 32]; aln = pAl[(kc + 1) * 32]; }

        uint32_t bh[8][2], bl[8][2];
        const unsigned kof = bbase + (unsigned)kc * 32;
#pragma unroll
        for (int nf = 0; nf < 8; nf++) {
            unsigned a = kof + (unsigned)nf * (8 * VSTRIDE);
            bh[nf][0] = *(const uint32_t*)(sm + a);
            bh[nf][1] = *(const uint32_t*)(sm + a + 16);
            bl[nf][0] = *(const uint32_t*)(sm + VOFF + a);
            bl[nf][1] = *(const uint32_t*)(sm + VOFF + a + 16);
        }
        const uint32_t* ar = (const uint32_t*)&ah;
        const uint32_t* alr = (const uint32_t*)&al;
#pragma unroll
        for (int nf = 0; nf < 8; nf++) {
            mma_bf16(acc[nf], ar,  bh[nf][0], bh[nf][1]);
            mma_bf16(acc[nf], ar,  bl[nf][0], bl[nf][1]);
            mma_bf16(acc[nf], alr, bh[nf][0], bh[nf][1]);
        }
        ah = ahn; al = aln;
    }

    // ---- write partials P[b*128 + j_local] ----
    float* P = g_part + (unsigned)(ks * NJG + jg) * (128 * BB);
    {
        const int j0 = band * 16 + (l >> 2);
        const int b0 = (l & 3) * 2;
#pragma unroll
        for (int nf = 0; nf < 8; nf++) {
            const int b = nf * 8 + b0;
            P[b * 128 + j0]           = acc[nf][0];
            P[(b + 1) * 128 + j0]     = acc[nf][1];
            P[b * 128 + j0 + 8]       = acc[nf][2];
            P[(b + 1) * 128 + j0 + 8] = acc[nf][3];
        }
    }

    __threadfence();
    __syncthreads();
    __shared__ unsigned sLast;
    if (tid == 0) {
        unsigned old = atomicAdd(&g_ticket[jg], 1u);
        sLast = (old == NKS - 1) ? 1u : 0u;
    }
    __syncthreads();

    if (sLast) {
        __threadfence();
        __nv_bfloat16* hh = g_hh[(t + 1) & 1];
        __nv_bfloat16* hl = g_hl[(t + 1) & 1];
        const bool last_t = (t == TT - 1);
        for (int o4 = tid; o4 < (128 * BB) / 4; o4 += NTHR) {
            float4 s = make_float4(0.f, 0.f, 0.f, 0.f);
#pragma unroll
            for (int kr = 0; kr < NKS; kr++) {
                const float4 v = *(const float4*)(g_part + (unsigned)(kr * NJG + jg) * (128 * BB) + o4 * 4);
                s.x += v.x; s.y += v.y; s.z += v.z; s.w += v.w;
            }
            s.x = tanhf(s.x); s.y = tanhf(s.y); s.z = tanhf(s.z); s.w = tanhf(s.w);
            const int o = o4 * 4;
            const int b = o >> 7;
            const int j0 = (o & 127) + jg * 128;
            float vals[4] = {s.x, s.y, s.z, s.w};
#pragma unroll
            for (int i = 0; i < 4; i++) {
                __nv_bfloat16 hi = __float2bfloat16(vals[i]);
                float r = vals[i] - __bfloat162float(hi);
                hh[b * HH + j0 + i] = hi;
                hl[b * HH + j0 + i] = __float2bfloat16(r);
            }
            if (last_t) *(float4*)&out[b * HH + j0] = s;
        }
        if (tid == 0) g_ticket[jg] = 0u;
    }
}

// ---------------- launcher ----------------
extern "C" void kernel_launch(void* const* d_in, const int* in_sizes, int n_in,
                              void* d_out, int out_size)
{
    const float* x    = (const float*)d_in[0];
    const float* Win  = (const float*)d_in[1];
    const float* Wres = (const float*)d_in[2];
    float* out = (float*)d_out;

    cudaFuncSetAttribute(esn_step, cudaFuncAttributeMaxDynamicSharedMemorySize, DYN_SMEM);

    esn_prep_w<<<2048, 256>>>(Win, Wres);
    esn_prep_x<<<2048, 256>>>(x);
    esn_init<<<128, 256>>>();
    for (int t = 0; t < TT; t++) {
        esn_step<<<NJG * NKS, NTHR, DYN_SMEM>>>(out, t);
    }
}

// round 4
// speedup vs baseline: 3.6876x; 1.3113x over previous
#include <cuda_runtime.h>
#include <cuda_bf16.h>
#include <cstdint>

// ESN: h_t = tanh(x_t @ W_in^T + h_{t-1} @ W_res^T); out = h_{T-1} [B,H] fp32.
// B=64, T=512, I=128, H=2048.
//
// Round 4: PERSISTENT kernel. One launch runs all 512 steps with hand-rolled
// grid barriers (grid=144 CTAs = one wave, 1 CTA/SM, all co-resident).
// Per step: stage v -> mma.sync bf16 x3 terms (fp32 emulation) -> partials ->
// grid barrier -> 128-CTA distributed reduce + tanh + h resplit -> barrier.

#define BB   64
#define TT   512
#define II   128
#define HH   2048
#define KTOT (II + HH)
#define NJG  16
#define NKS  9
#define KC1  256
#define NTHR 256
#define NCTA (NJG * NKS)         // 144
#define SLOT 131072              // per (jg,ks): 2 terms x up to 64KB
#define VSTRIDE 528              // padded bytes per b-row in smem
#define VOFF  (BB * VSTRIDE)     // 33792: offset of lo tile
#define DYN_SMEM (2 * BB * VSTRIDE)   // 67584

// ---------------- device globals ----------------
__device__ __align__(16) unsigned char  g_wa[NJG * NKS * SLOT];   // ~18.9MB frag-packed W
__device__ __align__(16) __nv_bfloat16  g_xh[BB * TT * II];
__device__ __align__(16) __nv_bfloat16  g_xl[BB * TT * II];
__device__ __align__(16) __nv_bfloat16  g_hh[BB * HH];
__device__ __align__(16) __nv_bfloat16  g_hl[BB * HH];
__device__ float    g_part[NKS * NJG * 128 * BB];
__device__ volatile unsigned g_bar;

// ---------------- mma helper ----------------
__device__ __forceinline__ void mma_bf16(float* d, const uint32_t* a,
                                         uint32_t b0, uint32_t b1) {
    asm volatile(
        "mma.sync.aligned.m16n8k16.row.col.f32.bf16.bf16.f32 "
        "{%0,%1,%2,%3}, {%4,%5,%6,%7}, {%8,%9}, {%0,%1,%2,%3};"
        : "+f"(d[0]), "+f"(d[1]), "+f"(d[2]), "+f"(d[3])
        : "r"(a[0]), "r"(a[1]), "r"(a[2]), "r"(a[3]), "r"(b0), "r"(b1));
}

// ---------------- grid barrier (all CTAs co-resident by construction) ----------
__device__ __forceinline__ void grid_sync(unsigned target) {
    __syncthreads();
    __threadfence();                       // order my writes before arrive
    if (threadIdx.x == 0) {
        atomicAdd((unsigned*)&g_bar, 1u);
        while (g_bar < target) { __nanosleep(64); }
    }
    __syncthreads();
    __threadfence();                       // invalidate stale L1 before reads
}

// ---------------- prep kernels ----------------
// Pack W (hi/lo bf16) into exact m16n8k16 A-fragment layout (see round 3).
__global__ void esn_prep_w(const float* __restrict__ Win, const float* __restrict__ Wres) {
    const int total = HH * KTOT;
    for (int idx = blockIdx.x * blockDim.x + threadIdx.x; idx < total;
         idx += gridDim.x * blockDim.x) {
        int j = idx / KTOT;
        int k = idx % KTOT;
        int jg = j >> 7, jl = j & 127;
        int ks, kl, kch;
        float w;
        if (k < II) { ks = 0; kl = k; kch = II >> 4; w = Win[j * II + k]; }
        else { int kk = k - II; ks = 1 + (kk >> 8); kl = kk & 255; kch = KC1 >> 4;
               w = Wres[j * HH + kk]; }
        __nv_bfloat16 hi = __float2bfloat16(w);
        float r = w - __bfloat162float(hi);
        __nv_bfloat16 lo = __float2bfloat16(r);

        int band = jl >> 4;
        int jr   = jl & 15;
        int kc   = kl >> 4;
        int kin  = kl & 15;
        int lane = ((jr & 7) << 2) | ((kin >> 1) & 3);
        int reg  = (jr >> 3) + ((kin >> 3) & 1) * 2;
        int half = kin & 1;
        unsigned off = (unsigned)(((band * kch + kc) * 32 + lane) * 16 + reg * 4 + half * 2);
        unsigned base = (unsigned)(jg * NKS + ks) * SLOT;
        unsigned tsz  = (unsigned)kch * 4096;
        *(__nv_bfloat16*)(g_wa + base + off)       = hi;
        *(__nv_bfloat16*)(g_wa + base + tsz + off) = lo;
    }
}

__global__ void esn_prep_x(const float* __restrict__ x) {
    const int total = BB * TT * II;
    for (int idx = blockIdx.x * blockDim.x + threadIdx.x; idx < total;
         idx += gridDim.x * blockDim.x) {
        float v = x[idx];
        __nv_bfloat16 hi = __float2bfloat16(v);
        float r = v - __bfloat162float(hi);
        g_xh[idx] = hi;
        g_xl[idx] = __float2bfloat16(r);
    }
}

__global__ void esn_bar0() { *(unsigned*)&g_bar = 0u; }

// ---------------- persistent kernel ----------------
__global__ __launch_bounds__(NTHR, 1) void esn_run(float* __restrict__ out) {
    extern __shared__ __align__(16) unsigned char sm[];

    const int tid  = threadIdx.x;
    const int band = tid >> 5;
    const int l    = tid & 31;
    const int bid  = blockIdx.x;
    const int jg   = bid / NKS;
    const int ks   = bid % NKS;
    const int KC   = ks ? KC1 : II;
    const int kch  = KC >> 4;
    const int cpb  = KC >> 3;                 // 16B chunks per b-row (stage)
    const int chunks = BB * cpb;

    // fixed A-fragment pointers (W is constant across steps; L2-resident)
    const unsigned slot = (unsigned)(jg * NKS + ks) * SLOT;
    const uint4* __restrict__ pAh = (const uint4*)(g_wa + slot) + (band * kch) * 32 + l;
    const uint4* __restrict__ pAl = pAh + (unsigned)kch * 256;

    const unsigned bbase = (unsigned)((l >> 2) * VSTRIDE + (l & 3) * 4);

    // reduce-phase assignment: 128 CTAs x 1024 outputs (1 float4/thread)
    const int r_jg = bid >> 3;
    const int r_o  = (bid & 7) * 1024 + tid * 4;     // o = b*128 + jl

    unsigned phase = 0;

    for (int t = 0; t < TT; t++) {
        // ---- stage v (hi/lo) into padded smem rows ----
        if (ks == 0) {
            for (int i = tid; i < chunks; i += NTHR) {
                int b = i / cpb, c = i - b * cpb;
                int e = (b * TT + t) * II + c * 8;
                unsigned d = (unsigned)(b * VSTRIDE + c * 16);
                *(uint4*)(sm + d)        = *(const uint4*)(g_xh + e);
                *(uint4*)(sm + VOFF + d) = *(const uint4*)(g_xl + e);
            }
        } else if (t == 0) {
            const uint4 z = make_uint4(0u, 0u, 0u, 0u);
            for (int i = tid; i < chunks; i += NTHR) {
                int b = i / cpb, c = i - b * cpb;
                unsigned d = (unsigned)(b * VSTRIDE + c * 16);
                *(uint4*)(sm + d)        = z;
                *(uint4*)(sm + VOFF + d) = z;
            }
        } else {
            for (int i = tid; i < chunks; i += NTHR) {
                int b = i / cpb, c = i - b * cpb;
                int e = b * HH + (ks - 1) * KC1 + c * 8;
                unsigned d = (unsigned)(b * VSTRIDE + c * 16);
                *(uint4*)(sm + d)        = *(const uint4*)(g_hh + e);
                *(uint4*)(sm + VOFF + d) = *(const uint4*)(g_hl + e);
            }
        }
        __syncthreads();

        // ---- MMA: warp = 16j x 64b, 3 terms (Wh*vh + Wh*vl + Wl*vh) ----
        float acc[8][4];
#pragma unroll
        for (int nf = 0; nf < 8; nf++)
#pragma unroll
            for (int i = 0; i < 4; i++) acc[nf][i] = 0.0f;

        uint4 ah = *pAh, al = *pAl;
        for (int kc = 0; kc < kch; kc++) {
            uint4 ahn, aln;
            if (kc + 1 < kch) { ahn = pAh[(kc + 1) * 32]; aln = pAl[(kc + 1) * 32]; }

            uint32_t bh[8][2], bl[8][2];
            const unsigned kof = bbase + (unsigned)kc * 32;
#pragma unroll
            for (int nf = 0; nf < 8; nf++) {
                unsigned a = kof + (unsigned)nf * (8 * VSTRIDE);
                bh[nf][0] = *(const uint32_t*)(sm + a);
                bh[nf][1] = *(const uint32_t*)(sm + a + 16);
                bl[nf][0] = *(const uint32_t*)(sm + VOFF + a);
                bl[nf][1] = *(const uint32_t*)(sm + VOFF + a + 16);
            }
            const uint32_t* ar  = (const uint32_t*)&ah;
            const uint32_t* alr = (const uint32_t*)&al;
#pragma unroll
            for (int nf = 0; nf < 8; nf++) {
                mma_bf16(acc[nf], ar,  bh[nf][0], bh[nf][1]);
                mma_bf16(acc[nf], ar,  bl[nf][0], bl[nf][1]);
                mma_bf16(acc[nf], alr, bh[nf][0], bh[nf][1]);
            }
            ah = ahn; al = aln;
        }

        // ---- write partials P[b*128 + j_local] ----
        {
            float* P = g_part + (unsigned)(ks * NJG + jg) * (128 * BB);
            const int j0 = band * 16 + (l >> 2);
            const int b0 = (l & 3) * 2;
#pragma unroll
            for (int nf = 0; nf < 8; nf++) {
                const int b = nf * 8 + b0;
                P[b * 128 + j0]           = acc[nf][0];
                P[(b + 1) * 128 + j0]     = acc[nf][1];
                P[b * 128 + j0 + 8]       = acc[nf][2];
                P[(b + 1) * 128 + j0 + 8] = acc[nf][3];
            }
        }

        grid_sync(++phase * NCTA);

        // ---- distributed reduce + tanh + resplit (128 CTAs) ----
        if (bid < 128) {
            float4 s = make_float4(0.f, 0.f, 0.f, 0.f);
            const float* Pb = g_part + (unsigned)r_jg * (128 * BB) + r_o;
#pragma unroll
            for (int kr = 0; kr < NKS; kr++) {
                const float4 v = *(const float4*)(Pb + (unsigned)kr * (NJG * 128 * BB));
                s.x += v.x; s.y += v.y; s.z += v.z; s.w += v.w;
            }
            s.x = tanhf(s.x); s.y = tanhf(s.y); s.z = tanhf(s.z); s.w = tanhf(s.w);

            const int b  = r_o >> 7;
            const int j  = r_jg * 128 + (r_o & 127);
            __nv_bfloat162 h01 = __floats2bfloat162_rn(s.x, s.y);
            __nv_bfloat162 h23 = __floats2bfloat162_rn(s.z, s.w);
            float r0 = s.x - __bfloat162float(__low2bfloat16(h01));
            float r1 = s.y - __bfloat162float(__high2bfloat16(h01));
            float r2 = s.z - __bfloat162float(__low2bfloat16(h23));
            float r3 = s.w - __bfloat162float(__high2bfloat16(h23));
            __nv_bfloat162 l01 = __floats2bfloat162_rn(r0, r1);
            __nv_bfloat162 l23 = __floats2bfloat162_rn(r2, r3);
            *(__nv_bfloat162*)(g_hh + b * HH + j)     = h01;
            *(__nv_bfloat162*)(g_hh + b * HH + j + 2) = h23;
            *(__nv_bfloat162*)(g_hl + b * HH + j)     = l01;
            *(__nv_bfloat162*)(g_hl + b * HH + j + 2) = l23;
            if (t == TT - 1) *(float4*)&out[b * HH + j] = s;
        }

        grid_sync(++phase * NCTA);
    }
}

// ---------------- launcher ----------------
extern "C" void kernel_launch(void* const* d_in, const int* in_sizes, int n_in,
                              void* d_out, int out_size)
{
    const float* x    = (const float*)d_in[0];
    const float* Win  = (const float*)d_in[1];
    const float* Wres = (const float*)d_in[2];
    float* out = (float*)d_out;

    cudaFuncSetAttribute(esn_run, cudaFuncAttributeMaxDynamicSharedMemorySize, DYN_SMEM);

    esn_prep_w<<<2048, 256>>>(Win, Wres);
    esn_prep_x<<<2048, 256>>>(x);
    esn_bar0<<<1, 1>>>();
    esn_run<<<NCTA, NTHR, DYN_SMEM>>>(out);
}

// round 5
// speedup vs baseline: 3.7557x; 1.0185x over previous
#include <cuda_runtime.h>
#include <cuda_bf16.h>
#include <cstdint>

// ESN: h_t = tanh(x_t @ W_in^T + h_{t-1} @ W_res^T); out = h_{T-1} [B,H] fp32.
// B=64, T=512, I=128, H=2048.
//
// Round 5: persistent kernel (144 CTAs, 2 grid barriers/step) with
//  - W (bf16 hi/lo) resident in SMEM for all 512 steps (no per-step W traffic,
//    immune to the L1 flush each gpu-scope fence performs)
//  - ldmatrix.x4 fragment loads for A and B (10 ldmatrix + 24 HMMA per warp-kc)
//  - coalesced split-K partial stores (P[j*64+b], STG.64, full-sector)
//  - reduce + tanh + bf16 hi/lo resplit with smem transpose for coalesced h I/O.

#define BB   64
#define TT   512
#define II   128
#define HH   2048
#define NJG  16
#define NKS  9
#define KC1  256
#define NTHR 256
#define NCTA (NJG * NKS)          // 144
#define ASTRIDE 528               // bytes per j-row (512 data + 16 pad)
#define TSZA (128 * ASTRIDE)      // 67584 per A term
#define BSTRIDE 528               // bytes per b-row
#define TSZB (BB * BSTRIDE)       // 33792 per B term
#define BOFF (2 * TSZA)           // B base in smem
#define SLOT (2 * TSZA)           // global W slot per (jg,ks)
#define DYN_SMEM (2 * TSZA + 2 * TSZB)   // 202752

// ---------------- device globals ----------------
__device__ __align__(16) unsigned char  g_wt[NCTA * SLOT];   // ~19.5MB padded W
__device__ __align__(16) __nv_bfloat16  g_xh[BB * TT * II];
__device__ __align__(16) __nv_bfloat16  g_xl[BB * TT * II];
__device__ __align__(16) __nv_bfloat16  g_hh[BB * HH];
__device__ __align__(16) __nv_bfloat16  g_hl[BB * HH];
__device__ float    g_part[NKS * NJG * 128 * BB];
__device__ volatile unsigned g_bar;

// ---------------- asm helpers ----------------
__device__ __forceinline__ void mma_bf16(float* d, const uint32_t* a,
                                         uint32_t b0, uint32_t b1) {
    asm volatile(
        "mma.sync.aligned.m16n8k16.row.col.f32.bf16.bf16.f32 "
        "{%0,%1,%2,%3}, {%4,%5,%6,%7}, {%8,%9}, {%0,%1,%2,%3};"
        : "+f"(d[0]), "+f"(d[1]), "+f"(d[2]), "+f"(d[3])
        : "r"(a[0]), "r"(a[1]), "r"(a[2]), "r"(a[3]), "r"(b0), "r"(b1));
}
__device__ __forceinline__ void ldmx4(uint32_t* r, uint32_t addr) {
    asm volatile("ldmatrix.sync.aligned.m8n8.x4.shared.b16 {%0,%1,%2,%3}, [%4];"
        : "=r"(r[0]), "=r"(r[1]), "=r"(r[2]), "=r"(r[3]) : "r"(addr));
}
__device__ __forceinline__ uint32_t smem_u32(const void* p) {
    uint32_t a;
    asm("{ .reg .u64 t; cvta.to.shared.u64 t, %1; cvt.u32.u64 %0, t; }"
        : "=r"(a) : "l"(p));
    return a;
}

// ---------------- grid barrier (all CTAs co-resident) ----------------
__device__ __forceinline__ void grid_sync(unsigned target) {
    __syncthreads();
    __threadfence();
    if (threadIdx.x == 0) {
        atomicAdd((unsigned*)&g_bar, 1u);
        while (g_bar < target) { __nanosleep(64); }
    }
    __syncthreads();
    __threadfence();
}

// ---------------- prep ----------------
// Plain padded layout: slot(jg,ks) + term*TSZA + jl*ASTRIDE + kl*2
__global__ void esn_prep_w(const float* __restrict__ Win, const float* __restrict__ Wres) {
    const int total = HH * (II + HH);
    for (int idx = blockIdx.x * blockDim.x + threadIdx.x; idx < total;
         idx += gridDim.x * blockDim.x) {
        int j = idx / (II + HH);
        int k = idx % (II + HH);
        int jg = j >> 7, jl = j & 127;
        int ks, kl;
        float w;
        if (k < II) { ks = 0; kl = k; w = Win[j * II + k]; }
        else { int kk = k - II; ks = 1 + (kk >> 8); kl = kk & 255; w = Wres[j * HH + kk]; }
        __nv_bfloat16 hi = __float2bfloat16(w);
        float r = w - __bfloat162float(hi);
        __nv_bfloat16 lo = __float2bfloat16(r);
        unsigned base = (unsigned)(jg * NKS + ks) * SLOT + (unsigned)jl * ASTRIDE + (unsigned)kl * 2;
        *(__nv_bfloat16*)(g_wt + base)        = hi;
        *(__nv_bfloat16*)(g_wt + base + TSZA) = lo;
    }
}

__global__ void esn_prep_x(const float* __restrict__ x) {
    const int total = BB * TT * II;
    for (int idx = blockIdx.x * blockDim.x + threadIdx.x; idx < total;
         idx += gridDim.x * blockDim.x) {
        float v = x[idx];
        __nv_bfloat16 hi = __float2bfloat16(v);
        float r = v - __bfloat162float(hi);
        g_xh[idx] = hi;
        g_xl[idx] = __float2bfloat16(r);
    }
}

__global__ void esn_bar0() { *(unsigned*)&g_bar = 0u; }

// ---------------- persistent kernel ----------------
__global__ __launch_bounds__(NTHR, 1) void esn_run(float* __restrict__ out) {
    extern __shared__ __align__(16) unsigned char sm[];
    __shared__ float sT[16 * 65];               // reduce transpose buffer

    const int tid  = threadIdx.x;
    const int band = tid >> 5;
    const int l    = tid & 31;
    const int bid  = blockIdx.x;
    const int jg   = bid / NKS;
    const int ks   = bid % NKS;
    const int KC   = ks ? KC1 : II;
    const int kch  = KC >> 4;
    const int cpb  = KC >> 3;                    // 16B chunks per b-row
    const int chunks = BB * cpb;

    const uint32_t smA = smem_u32(sm);
    const uint32_t smB = smA + BOFF;

    // ldmatrix lane base addresses
    // A tile (16j x 16k): row = band*16 + ((l>>3)&1)*8 + (l&7), kbyte += (l>>4)*16
    const uint32_t aA = smA + (uint32_t)(band * 16 + ((l >> 3) & 1) * 8 + (l & 7)) * ASTRIDE
                            + (uint32_t)(l >> 4) * 16;
    // B tile pair (16b x 16k): row = np*16 + ((l>>4)&1)*8 + (l&7), kbyte += ((l>>3)&1)*16
    const uint32_t aB = smB + (uint32_t)(((l >> 4) & 1) * 8 + (l & 7)) * BSTRIDE
                            + (uint32_t)((l >> 3) & 1) * 16;

    // ---- load W slot into smem once (persistent across all steps) ----
    {
        const uint4* src = (const uint4*)(g_wt + (unsigned)(jg * NKS + ks) * SLOT);
        uint4* dst = (uint4*)sm;
        for (int i = tid; i < SLOT / 16; i += NTHR) dst[i] = src[i];
    }

    // reduce-phase constants (CTAs 0..127)
    const int r_jg = bid >> 3;
    const int r_8  = bid & 7;
    const int jt   = tid >> 4;                   // 0..15 local j within 16-row tile
    const int b4   = (tid & 15) * 4;             // 0..60

    unsigned phase = 0;

    for (int t = 0; t < TT; t++) {
        // ---- stage v (hi/lo) rows into smem ----
        if (ks == 0) {
            for (int i = tid; i < chunks; i += NTHR) {
                int b = i / cpb, c = i - b * cpb;
                int e = (b * TT + t) * II + c * 8;
                uint32_t d = (uint32_t)(BOFF + b * BSTRIDE + c * 16);
                *(uint4*)(sm + d)        = *(const uint4*)(g_xh + e);
                *(uint4*)(sm + d + TSZB) = *(const uint4*)(g_xl + e);
            }
        } else if (t == 0) {
            const uint4 z = make_uint4(0u, 0u, 0u, 0u);
            for (int i = tid; i < chunks; i += NTHR) {
                int b = i / cpb, c = i - b * cpb;
                uint32_t d = (uint32_t)(BOFF + b * BSTRIDE + c * 16);
                *(uint4*)(sm + d)        = z;
                *(uint4*)(sm + d + TSZB) = z;
            }
        } else {
            for (int i = tid; i < chunks; i += NTHR) {
                int b = i / cpb, c = i - b * cpb;
                int e = b * HH + (ks - 1) * KC1 + c * 8;
                uint32_t d = (uint32_t)(BOFF + b * BSTRIDE + c * 16);
                *(uint4*)(sm + d)        = *(const uint4*)(g_hh + e);
                *(uint4*)(sm + d + TSZB) = *(const uint4*)(g_hl + e);
            }
        }
        __syncthreads();

        // ---- MMA: warp = 16j x 64b; 3 terms (Ah*Bh + Ah*Bl + Al*Bh) ----
        float acc[8][4];
#pragma unroll
        for (int nf = 0; nf < 8; nf++)
#pragma unroll
            for (int i = 0; i < 4; i++) acc[nf][i] = 0.0f;

#pragma unroll 4
        for (int kc = 0; kc < kch; kc++) {
            const uint32_t ka = (uint32_t)kc * 32;
            uint32_t Ah[4], Al[4], Bh[4][4], Bl[4][4];
            ldmx4(Ah, aA + ka);
            ldmx4(Al, aA + TSZA + ka);
#pragma unroll
            for (int np = 0; np < 4; np++) {
                const uint32_t ro = (uint32_t)np * (16 * BSTRIDE) + ka;
                ldmx4(Bh[np], aB + ro);
                ldmx4(Bl[np], aB + TSZB + ro);
            }
#pragma unroll
            for (int nf = 0; nf < 8; nf++) {
                const uint32_t bh0 = Bh[nf >> 1][(nf & 1) * 2];
                const uint32_t bh1 = Bh[nf >> 1][(nf & 1) * 2 + 1];
                const uint32_t bl0 = Bl[nf >> 1][(nf & 1) * 2];
                const uint32_t bl1 = Bl[nf >> 1][(nf & 1) * 2 + 1];
                mma_bf16(acc[nf], Ah, bh0, bh1);
                mma_bf16(acc[nf], Ah, bl0, bl1);
                mma_bf16(acc[nf], Al, bh0, bh1);
            }
        }

        // ---- coalesced partial stores: P[jl*64 + b] ----
        {
            float* P = g_part + (unsigned)(ks * NJG + jg) * (128 * BB);
            const int j0 = band * 16 + (l >> 2);
            const int b0 = (l & 3) * 2;
#pragma unroll
            for (int nf = 0; nf < 8; nf++) {
                const int b = nf * 8 + b0;
                *(float2*)&P[j0 * BB + b]       = make_float2(acc[nf][0], acc[nf][1]);
                *(float2*)&P[(j0 + 8) * BB + b] = make_float2(acc[nf][2], acc[nf][3]);
            }
        }

        grid_sync(++phase * NCTA);

        // ---- distributed reduce + tanh + resplit (CTAs 0..127) ----
        if (bid < 128) {
            const unsigned o = (unsigned)((r_8 * 16 + jt) * 64 + b4);
            float4 s = make_float4(0.f, 0.f, 0.f, 0.f);
#pragma unroll
            for (int kr = 0; kr < NKS; kr++) {
                const float4 v = *(const float4*)(g_part + (unsigned)(kr * NJG + r_jg) * (128 * BB) + o);
                s.x += v.x; s.y += v.y; s.z += v.z; s.w += v.w;
            }
            s.x = tanhf(s.x); s.y = tanhf(s.y); s.z = tanhf(s.z); s.w = tanhf(s.w);
            sT[jt * 65 + b4]     = s.x;
            sT[jt * 65 + b4 + 1] = s.y;
            sT[jt * 65 + b4 + 2] = s.z;
            sT[jt * 65 + b4 + 3] = s.w;
            __syncthreads();

            const bool last_t = (t == TT - 1);
#pragma unroll
            for (int it = 0; it < 2; it++) {
                const int idx2 = it * 256 + tid;       // 512 (j-pair, b) items
                const int p  = idx2 & 7;               // j pair
                const int bb = idx2 >> 3;              // batch
                const float f0 = sT[(2 * p) * 65 + bb];
                const float f1 = sT[(2 * p + 1) * 65 + bb];
                const int jglob = r_jg * 128 + r_8 * 16 + 2 * p;
                __nv_bfloat162 h2 = __floats2bfloat162_rn(f0, f1);
                float r0 = f0 - __bfloat162float(__low2bfloat16(h2));
                float r1 = f1 - __bfloat162float(__high2bfloat16(h2));
                __nv_bfloat162 l2 = __floats2bfloat162_rn(r0, r1);
                *(__nv_bfloat162*)(g_hh + bb * HH + jglob) = h2;
                *(__nv_bfloat162*)(g_hl + bb * HH + jglob) = l2;
                if (last_t) *(float2*)&out[bb * HH + jglob] = make_float2(f0, f1);
            }
        }

        grid_sync(++phase * NCTA);
    }
}

// ---------------- launcher ----------------
extern "C" void kernel_launch(void* const* d_in, const int* in_sizes, int n_in,
                              void* d_out, int out_size)
{
    const float* x    = (const float*)d_in[0];
    const float* Win  = (const float*)d_in[1];
    const float* Wres = (const float*)d_in[2];
    float* out = (float*)d_out;

    cudaFuncSetAttribute(esn_run, cudaFuncAttributeMaxDynamicSharedMemorySize, DYN_SMEM);

    esn_prep_w<<<2048, 256>>>(Win, Wres);
    esn_prep_x<<<2048, 256>>>(x);
    esn_bar0<<<1, 1>>>();
    esn_run<<<NCTA, NTHR, DYN_SMEM>>>(out);
}